// round 13
// baseline (speedup 1.0000x reference)
#include <cuda_runtime.h>
#include <math.h>
#include <stdint.h>

#define B 32
#define L 64
#define E 512
#define H 1024
#define G4 4096
#define V 32000

typedef unsigned int u32;
typedef unsigned short u16;
typedef unsigned long long u64;

// ---------------- scratch state (device globals; no allocs) ----------------
__device__ float d_h[B*H];               // decoder h (fp32, for attn)
__device__ float d_c[B*H];
__device__ u16   d_hbh[B*H];             // h as bf16 (GEMM A operand)
__device__ u16   d_cinbh[B*H];           // relu(combine) as bf16
__device__ float d_encouts[B*L*H];       // [b][l][j]
__device__ float d_xg[L][B][G4];         // precomputed emb@enc_wx + enc_b
__device__ float d_gpart[8][B][G4];      // K-split partials for gate GEMMs
__device__ float d_cpart[8][B][H];       // K-split partials for combine GEMM
__device__ float d_ctx[B*H];             // attention context
__device__ int   d_tok[B];
__device__ u32   d_owT[(size_t)V*512];   // out_w^T    [V][512]  bf16-pairs (64MB)
__device__ u32   d_whT[(size_t)G4*512];  // enc_wh^T   [4096][512]  (8MB)
__device__ u32   d_gwT[(size_t)G4*1024]; // [dec_wx;dec_wh]^T [4096][1024] (16MB)
__device__ u32   d_cwT[(size_t)H*1024];  // comb_w^T   [1024][1024] (4MB)
__device__ u32   d_xwT[(size_t)G4*256];  // enc_wx^T   [4096][256]  (4MB)
__device__ float d_lm2[B*250];           // per-(b,colchunk) max
__device__ float d_ls2[B*250];           // per-(b,colchunk) expsum
__device__ int   d_li2[B*250];           // per-(b,colchunk) argmax
__device__ float d_lseA[B*L];            // per-(b,t) log-sum-exp

__device__ __forceinline__ float sigmoidf_(float x){ return 1.f/(1.f+expf(-x)); }
__device__ __forceinline__ u32 f2bf(float f){ u32 b=__float_as_uint(f); return (b + 0x7fffu + ((b>>16)&1u))>>16; }

// classic tensor-core mma (sm_80+, suffix-free PTX -> compiles for sm_103)
__device__ __forceinline__ void mma_bf16(float* d, u32 a0,u32 a1,u32 a2,u32 a3,u32 b0,u32 b1){
  asm volatile("mma.sync.aligned.m16n8k16.row.col.f32.bf16.bf16.f32 "
    "{%0,%1,%2,%3}, {%4,%5,%6,%7}, {%8,%9}, {%0,%1,%2,%3};"
    : "+f"(d[0]),"+f"(d[1]),"+f"(d[2]),"+f"(d[3])
    : "r"(a0),"r"(a1),"r"(a2),"r"(a3),"r"(b0),"r"(b1));
}

// ---------------- init ----------------
__global__ void k_init(){
  int idx = blockIdx.x*256 + threadIdx.x;   // 32768 total
  d_h[idx]=0.f; d_c[idx]=0.f; d_hbh[idx]=0;
  if (idx < B) d_tok[idx] = 127;
}

// ---------------- one-time generic transpose-convert ----------------
// src fp32 [K][N] (row stride ns) -> dst u32 [N][kt] bf16-pairs at word offset k0w
__global__ void k_T(const float* __restrict__ src, int ns, u32* __restrict__ dst,
                    int kt, int k0w, int nblks){
  __shared__ float sh[64][65];
  int nb = blockIdx.x % nblks, kb = blockIdx.x / nblks;
  int n0 = nb*64, k0 = kb*64;
  int tid = threadIdx.x;
  int nc = tid & 63, kg = tid >> 6;
  #pragma unroll
  for (int r=0;r<16;r++){
    int kr = kg*16 + r;
    sh[kr][nc] = src[(size_t)(k0+kr)*ns + n0 + nc];
  }
  __syncthreads();
  int nl = tid >> 2, p0 = (tid & 3)*8;
  u32* d = dst + (size_t)(n0+nl)*kt + k0w + (k0>>1);
  #pragma unroll
  for (int q=0;q<8;q++){
    int p = p0 + q;
    d[p] = (f2bf(sh[2*p+1][nl])<<16) | f2bf(sh[2*p][nl]);
  }
}

// ---------------- one-time: xg[t] = emb(x_t) @ enc_wx + enc_b (bf16 mma) ----------------
// grid 2048 = 64 t x 32 colblk(128); 256 threads = 8 warps x 16 cols; K=512 in 4 chunks
__global__ void k_xg_mma(const int* __restrict__ x, const float* __restrict__ emb,
                         const float* __restrict__ eb){
  __shared__ u32 sA[32][68];
  __shared__ float sO[32][132];
  int tid = threadIdx.x, wid = tid>>5, lane = tid&31;
  int t = blockIdx.x >> 5;
  int colbase = (blockIdx.x & 31)*128;
  int g = lane>>2, q = lane&3;
  float acc[2][2][4] = {};
  const u32* wp = d_xwT + (size_t)(colbase + wid*16 + g)*256 + q;

  for (int kc=0;kc<4;kc++){
    int kb = kc*128;
    {
      int row = tid>>3, w0 = (tid&7)*8;
      int tok = x[row*L + t];
      const float2* ep = (const float2*)(emb + (size_t)tok*E + kb) + w0;
      #pragma unroll
      for (int i=0;i<8;i++){
        float2 v = ep[i];
        sA[row][w0+i] = (f2bf(v.y)<<16) | f2bf(v.x);
      }
    }
    __syncthreads();
    const u32* wkc = wp + kc*64;
    #pragma unroll
    for (int kss=0;kss<8;kss++){
      int kw = kss*8;
      u32 a00 = sA[g   ][kw+q],   a10 = sA[g+8 ][kw+q];
      u32 a20 = sA[g   ][kw+4+q], a30 = sA[g+8 ][kw+4+q];
      u32 a01 = sA[g+16][kw+q],   a11 = sA[g+24][kw+q];
      u32 a21 = sA[g+16][kw+4+q], a31 = sA[g+24][kw+4+q];
      #pragma unroll
      for (int j=0;j<2;j++){
        u32 b0 = wkc[j*8*256 + kw];
        u32 b1 = wkc[j*8*256 + kw + 4];
        mma_bf16(acc[0][j], a00,a10,a20,a30, b0,b1);
        mma_bf16(acc[1][j], a01,a11,a21,a31, b0,b1);
      }
    }
    __syncthreads();
  }
  #pragma unroll
  for (int m=0;m<2;m++)
    #pragma unroll
    for (int j=0;j<2;j++){
      int col = wid*16 + j*8 + q*2;
      *(float2*)&sO[g + m*16    ][col] = make_float2(acc[m][j][0], acc[m][j][1]);
      *(float2*)&sO[g + m*16 + 8][col] = make_float2(acc[m][j][2], acc[m][j][3]);
    }
  __syncthreads();
  int c0 = lane*4;
  float4 bb = *(const float4*)(eb + colbase + c0);
  #pragma unroll
  for (int rr=0;rr<4;rr++){
    int b = wid*4 + rr;
    float4 v = *(float4*)&sO[b][c0];
    v.x += bb.x; v.y += bb.y; v.z += bb.z; v.w += bb.w;
    *(float4*)&d_xg[t][b][colbase + c0] = v;
  }
}

// ---------------- generic bf16 mma GEMM: P[32 x 128cols] partials ----------------
// mode 0: enc gates  A=hbh          wT=d_whT kt=512  chunks=1 out=d_gpart stride G4
// mode 1: dec gates  A=cinbh|hbh    wT=d_gwT kt=1024 chunks=2 out=d_gpart stride G4
// mode 2: combine    A=e|ctx        wT=d_cwT kt=1024 chunks=2 out=d_cpart stride H
// grid = ncolblk*8 (ks = blockIdx.x & 7); 256 threads = 8 warps x 16 cols
__global__ void k_mm_bf16(int mode, const float* __restrict__ demb){
  __shared__ u32 sA[32][68];
  __shared__ float sO[32][132];
  int tid = threadIdx.x, wid = tid>>5, lane = tid&31;
  int ks = blockIdx.x & 7;
  int colbase = (blockIdx.x >> 3)*128;
  int g = lane>>2, q = lane&3;
  const u32* wT; int kt, chunks; float* outp; int ostride;
  if (mode == 0){ wT = d_whT; kt = 512;  chunks = 1; outp = &d_gpart[0][0][0]; ostride = G4; }
  else if (mode == 1){ wT = d_gwT; kt = 1024; chunks = 2; outp = &d_gpart[0][0][0]; ostride = G4; }
  else { wT = d_cwT; kt = 1024; chunks = 2; outp = &d_cpart[0][0][0]; ostride = H; }

  float acc[2][2][4] = {};
  const u32* wp = wT + (size_t)(colbase + wid*16 + g)*kt + q;

  for (int kc=0; kc<chunks; kc++){
    int kb = (ks*chunks + kc)*128;
    {
      int row = tid>>3, w0 = (tid&7)*8;
      if (mode == 0){
        const uint4* hp = (const uint4*)(d_hbh + row*H + kb + w0*2);
        *(uint4*)&sA[row][w0]   = hp[0];
        *(uint4*)&sA[row][w0+4] = hp[1];
      } else if (mode == 1){
        const u16* src = (kb < H) ? (d_cinbh + row*H + kb) : (d_hbh + row*H + kb - H);
        const uint4* hp = (const uint4*)(src + w0*2);
        *(uint4*)&sA[row][w0]   = hp[0];
        *(uint4*)&sA[row][w0+4] = hp[1];
      } else {
        if (kb < H){
          int tok = d_tok[row];
          const float2* ep = (const float2*)(demb + (size_t)tok*H + kb);
          #pragma unroll
          for (int i=0;i<8;i++){
            float2 v = ep[w0+i];
            sA[row][w0+i] = (f2bf(v.y)<<16) | f2bf(v.x);
          }
        } else {
          const float2* cp = (const float2*)(d_ctx + row*H + (kb-H));
          #pragma unroll
          for (int i=0;i<8;i++){
            float2 v = cp[w0+i];
            sA[row][w0+i] = (f2bf(v.y)<<16) | f2bf(v.x);
          }
        }
      }
    }
    __syncthreads();
    const u32* wkc = wp + (ks*chunks + kc)*64;
    #pragma unroll
    for (int kss=0;kss<8;kss++){
      int kw = kss*8;
      u32 a00 = sA[g   ][kw+q],   a10 = sA[g+8 ][kw+q];
      u32 a20 = sA[g   ][kw+4+q], a30 = sA[g+8 ][kw+4+q];
      u32 a01 = sA[g+16][kw+q],   a11 = sA[g+24][kw+q];
      u32 a21 = sA[g+16][kw+4+q], a31 = sA[g+24][kw+4+q];
      #pragma unroll
      for (int j=0;j<2;j++){
        u32 b0 = wkc[(size_t)j*8*kt + kw];
        u32 b1 = wkc[(size_t)j*8*kt + kw + 4];
        mma_bf16(acc[0][j], a00,a10,a20,a30, b0,b1);
        mma_bf16(acc[1][j], a01,a11,a21,a31, b0,b1);
      }
    }
    __syncthreads();
  }
  #pragma unroll
  for (int m=0;m<2;m++)
    #pragma unroll
    for (int j=0;j<2;j++){
      int col = wid*16 + j*8 + q*2;
      *(float2*)&sO[g + m*16    ][col] = make_float2(acc[m][j][0], acc[m][j][1]);
      *(float2*)&sO[g + m*16 + 8][col] = make_float2(acc[m][j][2], acc[m][j][3]);
    }
  __syncthreads();
  #pragma unroll
  for (int rr=0;rr<4;rr++){
    int b = wid*4 + rr;
    int c0 = lane*4;
    float4 v = *(float4*)&sO[b][c0];
    *(float4*)(outp + (size_t)(ks*B + b)*ostride + colbase + c0) = v;
  }
}

// ---------------- encoder pointwise ----------------
__global__ void k_enc_point(int t){
  int idx = blockIdx.x*256 + threadIdx.x;
  int b = idx >> 10, j = idx & 1023;
  float g0 = d_xg[t][b][j],      g1 = d_xg[t][b][j+1024];
  float g2 = d_xg[t][b][j+2048], g3 = d_xg[t][b][j+3072];
  #pragma unroll
  for (int p=0;p<8;p++){
    g0 += d_gpart[p][b][j];      g1 += d_gpart[p][b][j+1024];
    g2 += d_gpart[p][b][j+2048]; g3 += d_gpart[p][b][j+3072];
  }
  float c = d_c[idx];
  c = sigmoidf_(g1)*c + sigmoidf_(g0)*tanhf(g2);
  float h = sigmoidf_(g3)*tanhf(c);
  d_c[idx]=c;
  d_hbh[idx] = (u16)f2bf(h);
  d_encouts[(b*L + t)*H + j] = h;
}

// ---------------- fused attention: stats-merge -> token/lse, logits, softmax, ctx ------
// grid 32 (one block per batch row), 512 threads
__global__ void k_attn(const float* __restrict__ demb, const float* __restrict__ aw_w,
                       const float* __restrict__ ab, int t){
  __shared__ float sm[256]; __shared__ float ss[256]; __shared__ int si[256];
  __shared__ float sp[512];
  __shared__ float s_aw[64];
  __shared__ float s_red[2];
  __shared__ int s_tok;
  int b = blockIdx.x, tid = threadIdx.x;
  // head: merge previous step's 250 logit-chunk stats (launch boundary = sync)
  if (t > 0){
    if (tid < 256){
      float m = -INFINITY, s = 0.f; int mi = 0x7fffffff;
      if (tid < 250){ m = d_lm2[b*250+tid]; s = d_ls2[b*250+tid]; mi = d_li2[b*250+tid]; }
      sm[tid]=m; ss[tid]=s; si[tid]=mi;
    }
    __syncthreads();
    for (int st=128; st>0; st>>=1){
      if (tid < st){
        float m2 = sm[tid+st], s2 = ss[tid+st]; int i2 = si[tid+st];
        if (m2 > sm[tid]){ ss[tid] = ss[tid]*expf(sm[tid]-m2) + s2; sm[tid]=m2; si[tid]=i2; }
        else if (m2 > -INFINITY){ ss[tid] += s2*expf(m2-sm[tid]); if (m2 == sm[tid] && i2 < si[tid]) si[tid]=i2; }
      }
      __syncthreads();
    }
    if (tid == 0){
      s_tok = si[0];
      d_tok[b] = si[0];
      d_lseA[b*L + (t-1)] = sm[0] + logf(ss[0]);
    }
  } else {
    if (tid == 0) s_tok = d_tok[b];   // 127 from k_init
  }
  __syncthreads();
  int tok = s_tok;
  const float* erow = demb + (size_t)tok*H;
  // attention logits: 64 cols x 8 K-groups(256)
  int col = tid & 63, kg = tid >> 6;
  int k0 = kg*256;
  const float* arow = (k0 < H) ? (erow + k0) : (d_h + b*H + (k0-H));
  float acc = 0.f;
  #pragma unroll 4
  for (int i=0;i<256;i++) acc += arow[i] * aw_w[(size_t)(k0+i)*64 + col];
  sp[tid] = acc;
  __syncthreads();
  if (tid < 64){
    float lg = ab[tid];
    #pragma unroll
    for (int p=0;p<8;p++) lg += sp[tid + p*64];
    s_aw[tid] = lg;
  }
  __syncthreads();
  if (tid < 32){
    float m = fmaxf(s_aw[tid], s_aw[tid+32]);
    #pragma unroll
    for (int o=16;o>0;o>>=1) m = fmaxf(m, __shfl_xor_sync(0xffffffffu, m, o));
    if (tid==0) s_red[0]=m;
  }
  __syncthreads();
  if (tid < 64) s_aw[tid] = expf(s_aw[tid] - s_red[0]);
  __syncthreads();
  if (tid < 32){
    float s = s_aw[tid] + s_aw[tid+32];
    #pragma unroll
    for (int o=16;o>0;o>>=1) s += __shfl_xor_sync(0xffffffffu, s, o);
    if (tid==0) s_red[1]=s;
  }
  __syncthreads();
  float inv = 1.f / s_red[1];
  // ctx: 2 j per thread
  int j = tid*2;
  float cx = 0.f, cy = 0.f;
  #pragma unroll 4
  for (int l=0;l<64;l++){
    float w = s_aw[l]*inv;
    const float2 v = *(const float2*)&d_encouts[(b*L + l)*H + j];
    cx += w*v.x; cy += w*v.y;
  }
  *(float2*)&d_ctx[b*H + j] = make_float2(cx, cy);
}

// ---------------- combine finalize: reduce + bias + relu -> bf16 ----------------
__global__ void k_combfin(const float* __restrict__ cb){
  int idx = blockIdx.x*256 + threadIdx.x;
  int b = idx >> 10, j = idx & 1023;
  float s = cb[j];
  #pragma unroll
  for (int p=0;p<8;p++) s += d_cpart[p][b][j];
  d_cinbh[idx] = (u16)f2bf(fmaxf(s, 0.f));
}

// ---------------- decoder pointwise ----------------
__global__ void k_dec_point(const float* __restrict__ db){
  int idx = blockIdx.x*256 + threadIdx.x;
  int b = idx >> 10, j = idx & 1023;
  float g0 = db[j], g1 = db[j+1024], g2 = db[j+2048], g3 = db[j+3072];
  #pragma unroll
  for (int p=0;p<8;p++){
    g0 += d_gpart[p][b][j];      g1 += d_gpart[p][b][j+1024];
    g2 += d_gpart[p][b][j+2048]; g3 += d_gpart[p][b][j+3072];
  }
  float c = d_c[idx];
  c = sigmoidf_(g1)*c + sigmoidf_(g0)*tanhf(g2);
  float h = sigmoidf_(g3)*tanhf(c);
  d_c[idx]=c; d_h[idx]=h;
  d_hbh[idx] = (u16)f2bf(h);
}

// ---------------- logits via mma.sync bf16: D[32 x 128] per block ----------------
// grid 250 (128 vocab cols each); 256 threads = 8 warps (warp w: cols w*16..w*16+15)
__global__ void k_logits_mma(const float* __restrict__ ob, float* __restrict__ out, int t){
  __shared__ u32 sA[32][68];
  __shared__ float sLg[32][132];
  int tid = threadIdx.x, wid = tid>>5, lane = tid&31;
  int colbase = blockIdx.x*128;
  int g = lane>>2, q = lane&3;
  float acc[2][2][4];
  #pragma unroll
  for (int m=0;m<2;m++)
    #pragma unroll
    for (int j=0;j<2;j++)
      #pragma unroll
      for (int r=0;r<4;r++) acc[m][j][r]=0.f;

  const u32* wp = d_owT + (size_t)(colbase + wid*16 + g)*512 + q;

  for (int kc=0;kc<8;kc++){
    {
      int row = tid>>3, w0 = (tid&7)*8;
      const uint4* hp = (const uint4*)(d_hbh + row*H + kc*128 + w0*2);
      *(uint4*)&sA[row][w0]   = hp[0];
      *(uint4*)&sA[row][w0+4] = hp[1];
    }
    __syncthreads();
    const u32* wkc = wp + kc*64;
    #pragma unroll
    for (int ks=0;ks<8;ks++){
      int kw = ks*8;
      u32 a00 = sA[g   ][kw+q], a10 = sA[g+8 ][kw+q];
      u32 a20 = sA[g   ][kw+4+q], a30 = sA[g+8 ][kw+4+q];
      u32 a01 = sA[g+16][kw+q], a11 = sA[g+24][kw+q];
      u32 a21 = sA[g+16][kw+4+q], a31 = sA[g+24][kw+4+q];
      #pragma unroll
      for (int j=0;j<2;j++){
        u32 b0 = wkc[j*8*512 + kw];
        u32 b1 = wkc[j*8*512 + kw + 4];
        mma_bf16(acc[0][j], a00,a10,a20,a30, b0,b1);
        mma_bf16(acc[1][j], a01,a11,a21,a31, b0,b1);
      }
    }
    __syncthreads();
  }
  #pragma unroll
  for (int m=0;m<2;m++)
    #pragma unroll
    for (int j=0;j<2;j++){
      int col = wid*16 + j*8 + q*2;
      *(float2*)&sLg[g + m*16    ][col] = make_float2(acc[m][j][0], acc[m][j][1]);
      *(float2*)&sLg[g + m*16 + 8][col] = make_float2(acc[m][j][2], acc[m][j][3]);
    }
  __syncthreads();
  const float* bp = ob + colbase;
  float4 bb = *(const float4*)(bp + lane*4);
  #pragma unroll
  for (int rr=0;rr<4;rr++){
    int b = wid*4 + rr;
    int c0 = lane*4;
    float4 v = *(float4*)&sLg[b][c0];
    v.x += bb.x; v.y += bb.y; v.z += bb.z; v.w += bb.w;
    float* orow = out + ((size_t)(b*L + t))*V + colbase;
    *(float4*)(orow + c0) = v;
    float m = v.x; int mi = c0;
    if (v.y > m){ m=v.y; mi=c0+1; }
    if (v.z > m){ m=v.z; mi=c0+2; }
    if (v.w > m){ m=v.w; mi=c0+3; }
    #pragma unroll
    for (int o=16;o>0;o>>=1){
      float om = __shfl_xor_sync(0xffffffffu, m, o);
      int   oi = __shfl_xor_sync(0xffffffffu, mi, o);
      if (om > m || (om == m && oi < mi)){ m=om; mi=oi; }
    }
    float S = expf(v.x-m)+expf(v.y-m)+expf(v.z-m)+expf(v.w-m);
    #pragma unroll
    for (int o=16;o>0;o>>=1) S += __shfl_xor_sync(0xffffffffu, S, o);
    if (lane == 0){
      d_lm2[b*250 + blockIdx.x] = m;
      d_ls2[b*250 + blockIdx.x] = S;
      d_li2[b*250 + blockIdx.x] = colbase + mi;
    }
  }
}

// ---------------- final-step stats merge (t=63 lse + token unused) ----------------
// grid 32 (one block per batch row)
__global__ void k_tok(int t){
  __shared__ float sm[256]; __shared__ float ss[256]; __shared__ int si[256];
  int b = blockIdx.x, tid = threadIdx.x;
  float m = -INFINITY, s = 0.f; int mi = 0x7fffffff;
  for (int c = tid; c < 250; c += 256){
    float cm = d_lm2[b*250+c], cs = d_ls2[b*250+c]; int ci = d_li2[b*250+c];
    if (cm > m){ s = s*expf(m-cm) + cs; m = cm; mi = ci; }
    else { s += cs*expf(cm-m); if (cm == m && ci < mi) mi = ci; }
  }
  sm[tid]=m; ss[tid]=s; si[tid]=mi;
  __syncthreads();
  for (int st=128; st>0; st>>=1){
    if (tid < st){
      float m2 = sm[tid+st], s2 = ss[tid+st]; int i2 = si[tid+st];
      if (m2 > sm[tid]){ ss[tid] = ss[tid]*expf(sm[tid]-m2) + s2; sm[tid]=m2; si[tid]=i2; }
      else if (m2 > -INFINITY){ ss[tid] += s2*expf(m2-sm[tid]); if (m2 == sm[tid] && i2 < si[tid]) si[tid]=i2; }
    }
    __syncthreads();
  }
  if (tid == 0){
    d_tok[b] = si[0];
    d_lseA[b*L + t] = sm[0] + logf(ss[0]);
  }
}

// ---------------- final: subtract lse from every logit row ----------------
// grid 2048 (one block per (b,t) row)
__global__ void k_sub(float* __restrict__ out){
  int row = blockIdx.x;
  float lse = d_lseA[row];
  float4* p = (float4*)(out + (size_t)row*V);
  for (int i = threadIdx.x; i < V/4; i += 256){
    float4 v = p[i];
    v.x -= lse; v.y -= lse; v.z -= lse; v.w -= lse;
    p[i] = v;
  }
}

// ---------------- launcher ----------------
extern "C" void kernel_launch(void* const* d_in, const int* in_sizes, int n_in,
                              void* d_out, int out_size){
  const int*   x         = (const int*)  d_in[0];
  const float* enc_embed = (const float*)d_in[1];
  const float* enc_wx    = (const float*)d_in[2];
  const float* enc_wh    = (const float*)d_in[3];
  const float* enc_b     = (const float*)d_in[4];
  const float* dec_embed = (const float*)d_in[5];
  const float* attn_w    = (const float*)d_in[6];
  const float* attn_b    = (const float*)d_in[7];
  const float* comb_w    = (const float*)d_in[8];
  const float* comb_b    = (const float*)d_in[9];
  const float* dec_wx    = (const float*)d_in[10];
  const float* dec_wh    = (const float*)d_in[11];
  const float* dec_b     = (const float*)d_in[12];
  const float* out_w     = (const float*)d_in[13];
  const float* out_b     = (const float*)d_in[14];
  float* out = (float*)d_out;

  u32 *p_owT, *p_whT, *p_gwT, *p_cwT, *p_xwT;
  cudaGetSymbolAddress((void**)&p_owT, d_owT);
  cudaGetSymbolAddress((void**)&p_whT, d_whT);
  cudaGetSymbolAddress((void**)&p_gwT, d_gwT);
  cudaGetSymbolAddress((void**)&p_cwT, d_cwT);
  cudaGetSymbolAddress((void**)&p_xwT, d_xwT);

  k_init<<<128,256>>>();
  k_T<<<500*16,256>>>(out_w,   V,  p_owT, 512,  0,   500);  // out_w^T
  k_T<<<64*16, 256>>>(enc_wh,  G4, p_whT, 512,  0,   64);   // enc_wh^T
  k_T<<<64*16, 256>>>(dec_wx,  G4, p_gwT, 1024, 0,   64);   // dec_wx^T (K 0..1023)
  k_T<<<64*16, 256>>>(dec_wh,  G4, p_gwT, 1024, 512, 64);   // dec_wh^T (K 1024..2047)
  k_T<<<16*32, 256>>>(comb_w,  H,  p_cwT, 1024, 0,   16);   // comb_w^T
  k_T<<<64*8,  256>>>(enc_wx,  G4, p_xwT, 256,  0,   64);   // enc_wx^T
  k_xg_mma<<<2048,256>>>(x, enc_embed, enc_b);
  for (int t=0;t<64;t++){
    k_mm_bf16<<<256,256>>>(0, nullptr);           // h @ enc_wh -> gpart
    k_enc_point<<<128,256>>>(t);
  }
  k_init<<<128,256>>>();
  for (int t=0;t<64;t++){
    k_attn<<<32,512>>>(dec_embed, attn_w, attn_b, t);  // stats->tok/lse + attn + ctx
    k_mm_bf16<<<64,256>>>(2, dec_embed);               // concat(e,ctx) @ comb_w -> cpart
    k_combfin<<<128,256>>>(comb_b);
    k_mm_bf16<<<256,256>>>(1, nullptr);                // concat(cin,h) @ [wx;wh] -> gpart
    k_dec_point<<<128,256>>>(dec_b);
    k_logits_mma<<<250,256>>>(out_b, out, t);
  }
  k_tok<<<32,256>>>(63);
  k_sub<<<2048,256>>>(out);
}

// round 14
// speedup vs baseline: 1.1743x; 1.1743x over previous
#include <cuda_runtime.h>
#include <math.h>
#include <stdint.h>

#define B 32
#define L 64
#define E 512
#define H 1024
#define G4 4096
#define V 32000

typedef unsigned int u32;
typedef unsigned short u16;
typedef unsigned long long u64;

// ---------------- scratch state (device globals; no allocs) ----------------
__device__ float d_h[B*H];               // decoder h (fp32, for attn)
__device__ float d_c[B*H];
__device__ u16   d_hbh[B*H];             // h as bf16 (GEMM A operand)
__device__ u16   d_cinbh[B*H];           // relu(combine) as bf16
__device__ float d_encouts[B*L*H];       // [b][l][j]
__device__ float d_xg[L][B][G4];         // precomputed emb@enc_wx + enc_b
__device__ float d_gpart[8][B][G4];      // K-split partials for gate GEMMs
__device__ float d_cpart[8][B][H];       // K-split partials for combine GEMM
__device__ float d_ctx[B*H];             // attention context
__device__ float d_apart[8][B][64];      // attention logit partials
__device__ int   d_tok[B];
__device__ u32   d_owT[(size_t)V*512];   // out_w^T    [V][512]  bf16-pairs (64MB)
__device__ u32   d_whT[(size_t)G4*512];  // enc_wh^T   [4096][512]  (8MB)
__device__ u32   d_gwT[(size_t)G4*1024]; // [dec_wx;dec_wh]^T [4096][1024] (16MB)
__device__ u32   d_cwT[(size_t)H*1024];  // comb_w^T   [1024][1024] (4MB)
__device__ u32   d_xwT[(size_t)G4*256];  // enc_wx^T   [4096][256]  (4MB)
__device__ float d_lm2[B*250];           // per-(b,colchunk) max
__device__ float d_ls2[B*250];           // per-(b,colchunk) expsum
__device__ int   d_li2[B*250];           // per-(b,colchunk) argmax
__device__ float d_lseA[B*L];            // per-(b,t) log-sum-exp

__device__ __forceinline__ float sigmoidf_(float x){ return 1.f/(1.f+expf(-x)); }
__device__ __forceinline__ u32 f2bf(float f){ u32 b=__float_as_uint(f); return (b + 0x7fffu + ((b>>16)&1u))>>16; }

// classic tensor-core mma (sm_80+, suffix-free PTX -> compiles for sm_103)
__device__ __forceinline__ void mma_bf16(float* d, u32 a0,u32 a1,u32 a2,u32 a3,u32 b0,u32 b1){
  asm volatile("mma.sync.aligned.m16n8k16.row.col.f32.bf16.bf16.f32 "
    "{%0,%1,%2,%3}, {%4,%5,%6,%7}, {%8,%9}, {%0,%1,%2,%3};"
    : "+f"(d[0]),"+f"(d[1]),"+f"(d[2]),"+f"(d[3])
    : "r"(a0),"r"(a1),"r"(a2),"r"(a3),"r"(b0),"r"(b1));
}

// ---------------- init ----------------
__global__ void k_init(){
  int idx = blockIdx.x*256 + threadIdx.x;   // 32768 total
  d_h[idx]=0.f; d_c[idx]=0.f; d_hbh[idx]=0;
  if (idx < B) d_tok[idx] = 127;
}

// ---------------- one-time generic transpose-convert ----------------
// src fp32 [K][N] (row stride ns) -> dst u32 [N][kt] bf16-pairs at word offset k0w
__global__ void k_T(const float* __restrict__ src, int ns, u32* __restrict__ dst,
                    int kt, int k0w, int nblks){
  __shared__ float sh[64][65];
  int nb = blockIdx.x % nblks, kb = blockIdx.x / nblks;
  int n0 = nb*64, k0 = kb*64;
  int tid = threadIdx.x;
  int nc = tid & 63, kg = tid >> 6;
  #pragma unroll
  for (int r=0;r<16;r++){
    int kr = kg*16 + r;
    sh[kr][nc] = src[(size_t)(k0+kr)*ns + n0 + nc];
  }
  __syncthreads();
  int nl = tid >> 2, p0 = (tid & 3)*8;
  u32* d = dst + (size_t)(n0+nl)*kt + k0w + (k0>>1);
  #pragma unroll
  for (int q=0;q<8;q++){
    int p = p0 + q;
    d[p] = (f2bf(sh[2*p+1][nl])<<16) | f2bf(sh[2*p][nl]);
  }
}

// ---------------- one-time: xg[t] = emb(x_t) @ enc_wx + enc_b (bf16 mma) ----------------
// grid 2048 = 64 t x 32 colblk(128); 256 threads = 8 warps x 16 cols; K=512 in 4 chunks
__global__ void k_xg_mma(const int* __restrict__ x, const float* __restrict__ emb,
                         const float* __restrict__ eb){
  __shared__ u32 sA[32][68];
  __shared__ float sO[32][132];
  int tid = threadIdx.x, wid = tid>>5, lane = tid&31;
  int t = blockIdx.x >> 5;
  int colbase = (blockIdx.x & 31)*128;
  int g = lane>>2, q = lane&3;
  float acc[2][2][4] = {};
  const u32* wp = d_xwT + (size_t)(colbase + wid*16 + g)*256 + q;

  for (int kc=0;kc<4;kc++){
    int kb = kc*128;
    {
      int row = tid>>3, w0 = (tid&7)*8;
      int tok = x[row*L + t];
      const float2* ep = (const float2*)(emb + (size_t)tok*E + kb) + w0;
      #pragma unroll
      for (int i=0;i<8;i++){
        float2 v = ep[i];
        sA[row][w0+i] = (f2bf(v.y)<<16) | f2bf(v.x);
      }
    }
    __syncthreads();
    const u32* wkc = wp + kc*64;
    #pragma unroll
    for (int kss=0;kss<8;kss++){
      int kw = kss*8;
      u32 a00 = sA[g   ][kw+q],   a10 = sA[g+8 ][kw+q];
      u32 a20 = sA[g   ][kw+4+q], a30 = sA[g+8 ][kw+4+q];
      u32 a01 = sA[g+16][kw+q],   a11 = sA[g+24][kw+q];
      u32 a21 = sA[g+16][kw+4+q], a31 = sA[g+24][kw+4+q];
      #pragma unroll
      for (int j=0;j<2;j++){
        u32 b0 = wkc[j*8*256 + kw];
        u32 b1 = wkc[j*8*256 + kw + 4];
        mma_bf16(acc[0][j], a00,a10,a20,a30, b0,b1);
        mma_bf16(acc[1][j], a01,a11,a21,a31, b0,b1);
      }
    }
    __syncthreads();
  }
  #pragma unroll
  for (int m=0;m<2;m++)
    #pragma unroll
    for (int j=0;j<2;j++){
      int col = wid*16 + j*8 + q*2;
      *(float2*)&sO[g + m*16    ][col] = make_float2(acc[m][j][0], acc[m][j][1]);
      *(float2*)&sO[g + m*16 + 8][col] = make_float2(acc[m][j][2], acc[m][j][3]);
    }
  __syncthreads();
  int c0 = lane*4;
  float4 bb = *(const float4*)(eb + colbase + c0);
  #pragma unroll
  for (int rr=0;rr<4;rr++){
    int b = wid*4 + rr;
    float4 v = *(float4*)&sO[b][c0];
    v.x += bb.x; v.y += bb.y; v.z += bb.z; v.w += bb.w;
    *(float4*)&d_xg[t][b][colbase + c0] = v;
  }
}

// ---------------- generic bf16 mma GEMM: P[32 x 128cols] partials ----------------
// mode 0: enc gates  A=hbh          wT=d_whT kt=512  chunks=1 out=d_gpart stride G4
// mode 1: dec gates  A=cinbh|hbh    wT=d_gwT kt=1024 chunks=2 out=d_gpart stride G4
// mode 2: combine    A=e|ctx        wT=d_cwT kt=1024 chunks=2 out=d_cpart stride H
// grid = ncolblk*8 (ks = blockIdx.x & 7); 256 threads = 8 warps x 16 cols
__global__ void k_mm_bf16(int mode, const float* __restrict__ demb){
  __shared__ u32 sA[32][68];
  __shared__ float sO[32][132];
  int tid = threadIdx.x, wid = tid>>5, lane = tid&31;
  int ks = blockIdx.x & 7;
  int colbase = (blockIdx.x >> 3)*128;
  int g = lane>>2, q = lane&3;
  const u32* wT; int kt, chunks; float* outp; int ostride;
  if (mode == 0){ wT = d_whT; kt = 512;  chunks = 1; outp = &d_gpart[0][0][0]; ostride = G4; }
  else if (mode == 1){ wT = d_gwT; kt = 1024; chunks = 2; outp = &d_gpart[0][0][0]; ostride = G4; }
  else { wT = d_cwT; kt = 1024; chunks = 2; outp = &d_cpart[0][0][0]; ostride = H; }

  float acc[2][2][4] = {};
  const u32* wp = wT + (size_t)(colbase + wid*16 + g)*kt + q;

  for (int kc=0; kc<chunks; kc++){
    int kb = (ks*chunks + kc)*128;
    {
      int row = tid>>3, w0 = (tid&7)*8;
      if (mode == 0){
        const uint4* hp = (const uint4*)(d_hbh + row*H + kb + w0*2);
        *(uint4*)&sA[row][w0]   = hp[0];
        *(uint4*)&sA[row][w0+4] = hp[1];
      } else if (mode == 1){
        const u16* src = (kb < H) ? (d_cinbh + row*H + kb) : (d_hbh + row*H + kb - H);
        const uint4* hp = (const uint4*)(src + w0*2);
        *(uint4*)&sA[row][w0]   = hp[0];
        *(uint4*)&sA[row][w0+4] = hp[1];
      } else {
        if (kb < H){
          int tok = d_tok[row];
          const float2* ep = (const float2*)(demb + (size_t)tok*H + kb);
          #pragma unroll
          for (int i=0;i<8;i++){
            float2 v = ep[w0+i];
            sA[row][w0+i] = (f2bf(v.y)<<16) | f2bf(v.x);
          }
        } else {
          const float2* cp = (const float2*)(d_ctx + row*H + (kb-H));
          #pragma unroll
          for (int i=0;i<8;i++){
            float2 v = cp[w0+i];
            sA[row][w0+i] = (f2bf(v.y)<<16) | f2bf(v.x);
          }
        }
      }
    }
    __syncthreads();
    const u32* wkc = wp + (ks*chunks + kc)*64;
    #pragma unroll
    for (int kss=0;kss<8;kss++){
      int kw = kss*8;
      u32 a00 = sA[g   ][kw+q],   a10 = sA[g+8 ][kw+q];
      u32 a20 = sA[g   ][kw+4+q], a30 = sA[g+8 ][kw+4+q];
      u32 a01 = sA[g+16][kw+q],   a11 = sA[g+24][kw+q];
      u32 a21 = sA[g+16][kw+4+q], a31 = sA[g+24][kw+4+q];
      #pragma unroll
      for (int j=0;j<2;j++){
        u32 b0 = wkc[(size_t)j*8*kt + kw];
        u32 b1 = wkc[(size_t)j*8*kt + kw + 4];
        mma_bf16(acc[0][j], a00,a10,a20,a30, b0,b1);
        mma_bf16(acc[1][j], a01,a11,a21,a31, b0,b1);
      }
    }
    __syncthreads();
  }
  #pragma unroll
  for (int m=0;m<2;m++)
    #pragma unroll
    for (int j=0;j<2;j++){
      int col = wid*16 + j*8 + q*2;
      *(float2*)&sO[g + m*16    ][col] = make_float2(acc[m][j][0], acc[m][j][1]);
      *(float2*)&sO[g + m*16 + 8][col] = make_float2(acc[m][j][2], acc[m][j][3]);
    }
  __syncthreads();
  #pragma unroll
  for (int rr=0;rr<4;rr++){
    int b = wid*4 + rr;
    int c0 = lane*4;
    float4 v = *(float4*)&sO[b][c0];
    *(float4*)(outp + (size_t)(ks*B + b)*ostride + colbase + c0) = v;
  }
}

// ---------------- encoder pointwise ----------------
__global__ void k_enc_point(int t){
  int idx = blockIdx.x*256 + threadIdx.x;
  int b = idx >> 10, j = idx & 1023;
  float g0 = d_xg[t][b][j],      g1 = d_xg[t][b][j+1024];
  float g2 = d_xg[t][b][j+2048], g3 = d_xg[t][b][j+3072];
  #pragma unroll
  for (int p=0;p<8;p++){
    g0 += d_gpart[p][b][j];      g1 += d_gpart[p][b][j+1024];
    g2 += d_gpart[p][b][j+2048]; g3 += d_gpart[p][b][j+3072];
  }
  float c = d_c[idx];
  c = sigmoidf_(g1)*c + sigmoidf_(g0)*tanhf(g2);
  float h = sigmoidf_(g3)*tanhf(c);
  d_c[idx]=c;
  d_hbh[idx] = (u16)f2bf(h);
  d_encouts[(b*L + t)*H + j] = h;
}

// ---------------- attention phase 1 (+ fused prev-step stats merge) ----------------
// grid 256 = 32 b x 8 ks (256 K each); 256 threads
__global__ void k_attn1(const float* __restrict__ demb, const float* __restrict__ aw_w,
                        int t){
  __shared__ float sm[256]; __shared__ float ss[256]; __shared__ int si[256];
  __shared__ float sp[256];
  int b = blockIdx.x >> 3, ks = blockIdx.x & 7;
  int tid = threadIdx.x;
  int tok;
  if (t > 0){
    // merge previous step's 250 logit-chunk stats (launch boundary = data ready)
    float m = -INFINITY, s = 0.f; int mi = 0x7fffffff;
    if (tid < 250){ m = d_lm2[b*250+tid]; s = d_ls2[b*250+tid]; mi = d_li2[b*250+tid]; }
    sm[tid]=m; ss[tid]=s; si[tid]=mi;
    __syncthreads();
    for (int st=128; st>0; st>>=1){
      if (tid < st){
        float m2 = sm[tid+st], s2 = ss[tid+st]; int i2 = si[tid+st];
        if (m2 > sm[tid]){ ss[tid] = ss[tid]*expf(sm[tid]-m2) + s2; sm[tid]=m2; si[tid]=i2; }
        else if (m2 > -INFINITY){ ss[tid] += s2*expf(m2-sm[tid]); if (m2 == sm[tid] && i2 < si[tid]) si[tid]=i2; }
      }
      __syncthreads();
    }
    tok = si[0];
    if (ks == 0 && tid == 0){
      d_tok[b] = tok;                              // for combine loader (next launch)
      d_lseA[b*L + (t-1)] = sm[0] + logf(ss[0]);
    }
    __syncthreads();
  } else {
    tok = 127;
  }
  const float* erow = demb + (size_t)tok*H;
  int col = tid & 63, kg = tid >> 6;
  int k0 = ks*256 + kg*64;
  float acc = 0.f;
  const float* arow = (k0 < H) ? (erow + k0) : (d_h + b*H + (k0-H));
  #pragma unroll 4
  for (int i=0;i<64;i++) acc += arow[i] * aw_w[(size_t)(k0+i)*64 + col];
  sp[tid] = acc;
  __syncthreads();
  if (tid < 64) d_apart[ks][b][tid] = sp[tid] + sp[tid+64] + sp[tid+128] + sp[tid+192];
}

// ---------------- attention phase 2: softmax + context ----------------
// grid 128 = 32 b x 4 jblk (256 j each)
__global__ void k_attn_ctx(const float* __restrict__ ab){
  __shared__ float s_aw[64];
  __shared__ float s_red[2];
  int b = blockIdx.x >> 2, jblk = blockIdx.x & 3;
  int tid = threadIdx.x;
  if (tid < 64){
    float lg = ab[tid];
    #pragma unroll
    for (int p=0;p<8;p++) lg += d_apart[p][b][tid];
    s_aw[tid] = lg;
  }
  __syncthreads();
  if (tid < 32){
    float m = fmaxf(s_aw[tid], s_aw[tid+32]);
    #pragma unroll
    for (int o=16;o>0;o>>=1) m = fmaxf(m, __shfl_xor_sync(0xffffffffu, m, o));
    if (tid==0) s_red[0]=m;
  }
  __syncthreads();
  if (tid < 64) s_aw[tid] = expf(s_aw[tid] - s_red[0]);
  __syncthreads();
  if (tid < 32){
    float s = s_aw[tid] + s_aw[tid+32];
    #pragma unroll
    for (int o=16;o>0;o>>=1) s += __shfl_xor_sync(0xffffffffu, s, o);
    if (tid==0) s_red[1]=s;
  }
  __syncthreads();
  float inv = 1.f / s_red[1];
  int j = jblk*256 + tid;
  float c = 0.f;
  #pragma unroll 4
  for (int l=0;l<64;l++) c += s_aw[l]*inv * d_encouts[(b*L + l)*H + j];
  d_ctx[b*H + j] = c;
}

// ---------------- combine finalize: reduce + bias + relu -> bf16 ----------------
__global__ void k_combfin(const float* __restrict__ cb){
  int idx = blockIdx.x*256 + threadIdx.x;
  int b = idx >> 10, j = idx & 1023;
  float s = cb[j];
  #pragma unroll
  for (int p=0;p<8;p++) s += d_cpart[p][b][j];
  d_cinbh[idx] = (u16)f2bf(fmaxf(s, 0.f));
}

// ---------------- decoder pointwise ----------------
__global__ void k_dec_point(const float* __restrict__ db){
  int idx = blockIdx.x*256 + threadIdx.x;
  int b = idx >> 10, j = idx & 1023;
  float g0 = db[j], g1 = db[j+1024], g2 = db[j+2048], g3 = db[j+3072];
  #pragma unroll
  for (int p=0;p<8;p++){
    g0 += d_gpart[p][b][j];      g1 += d_gpart[p][b][j+1024];
    g2 += d_gpart[p][b][j+2048]; g3 += d_gpart[p][b][j+3072];
  }
  float c = d_c[idx];
  c = sigmoidf_(g1)*c + sigmoidf_(g0)*tanhf(g2);
  float h = sigmoidf_(g3)*tanhf(c);
  d_c[idx]=c; d_h[idx]=h;
  d_hbh[idx] = (u16)f2bf(h);
}

// ---------------- logits via mma.sync bf16: D[32 x 128] per block ----------------
// grid 250 (128 vocab cols each); 256 threads = 8 warps (warp w: cols w*16..w*16+15)
__global__ void k_logits_mma(const float* __restrict__ ob, float* __restrict__ out, int t){
  __shared__ u32 sA[32][68];
  __shared__ float sLg[32][132];
  int tid = threadIdx.x, wid = tid>>5, lane = tid&31;
  int colbase = blockIdx.x*128;
  int g = lane>>2, q = lane&3;
  float acc[2][2][4];
  #pragma unroll
  for (int m=0;m<2;m++)
    #pragma unroll
    for (int j=0;j<2;j++)
      #pragma unroll
      for (int r=0;r<4;r++) acc[m][j][r]=0.f;

  const u32* wp = d_owT + (size_t)(colbase + wid*16 + g)*512 + q;

  for (int kc=0;kc<8;kc++){
    {
      int row = tid>>3, w0 = (tid&7)*8;
      const uint4* hp = (const uint4*)(d_hbh + row*H + kc*128 + w0*2);
      *(uint4*)&sA[row][w0]   = hp[0];
      *(uint4*)&sA[row][w0+4] = hp[1];
    }
    __syncthreads();
    const u32* wkc = wp + kc*64;
    #pragma unroll
    for (int ks=0;ks<8;ks++){
      int kw = ks*8;
      u32 a00 = sA[g   ][kw+q], a10 = sA[g+8 ][kw+q];
      u32 a20 = sA[g   ][kw+4+q], a30 = sA[g+8 ][kw+4+q];
      u32 a01 = sA[g+16][kw+q], a11 = sA[g+24][kw+q];
      u32 a21 = sA[g+16][kw+4+q], a31 = sA[g+24][kw+4+q];
      #pragma unroll
      for (int j=0;j<2;j++){
        u32 b0 = wkc[j*8*512 + kw];
        u32 b1 = wkc[j*8*512 + kw + 4];
        mma_bf16(acc[0][j], a00,a10,a20,a30, b0,b1);
        mma_bf16(acc[1][j], a01,a11,a21,a31, b0,b1);
      }
    }
    __syncthreads();
  }
  #pragma unroll
  for (int m=0;m<2;m++)
    #pragma unroll
    for (int j=0;j<2;j++){
      int col = wid*16 + j*8 + q*2;
      *(float2*)&sLg[g + m*16    ][col] = make_float2(acc[m][j][0], acc[m][j][1]);
      *(float2*)&sLg[g + m*16 + 8][col] = make_float2(acc[m][j][2], acc[m][j][3]);
    }
  __syncthreads();
  const float* bp = ob + colbase;
  float4 bb = *(const float4*)(bp + lane*4);
  #pragma unroll
  for (int rr=0;rr<4;rr++){
    int b = wid*4 + rr;
    int c0 = lane*4;
    float4 v = *(float4*)&sLg[b][c0];
    v.x += bb.x; v.y += bb.y; v.z += bb.z; v.w += bb.w;
    float* orow = out + ((size_t)(b*L + t))*V + colbase;
    *(float4*)(orow + c0) = v;
    float m = v.x; int mi = c0;
    if (v.y > m){ m=v.y; mi=c0+1; }
    if (v.z > m){ m=v.z; mi=c0+2; }
    if (v.w > m){ m=v.w; mi=c0+3; }
    #pragma unroll
    for (int o=16;o>0;o>>=1){
      float om = __shfl_xor_sync(0xffffffffu, m, o);
      int   oi = __shfl_xor_sync(0xffffffffu, mi, o);
      if (om > m || (om == m && oi < mi)){ m=om; mi=oi; }
    }
    float S = expf(v.x-m)+expf(v.y-m)+expf(v.z-m)+expf(v.w-m);
    #pragma unroll
    for (int o=16;o>0;o>>=1) S += __shfl_xor_sync(0xffffffffu, S, o);
    if (lane == 0){
      d_lm2[b*250 + blockIdx.x] = m;
      d_ls2[b*250 + blockIdx.x] = S;
      d_li2[b*250 + blockIdx.x] = colbase + mi;
    }
  }
}

// ---------------- final-step stats merge (t=63 lse) ----------------
// grid 32 (one block per batch row)
__global__ void k_tok(int t){
  __shared__ float sm[256]; __shared__ float ss[256]; __shared__ int si[256];
  int b = blockIdx.x, tid = threadIdx.x;
  float m = -INFINITY, s = 0.f; int mi = 0x7fffffff;
  for (int c = tid; c < 250; c += 256){
    float cm = d_lm2[b*250+c], cs = d_ls2[b*250+c]; int ci = d_li2[b*250+c];
    if (cm > m){ s = s*expf(m-cm) + cs; m = cm; mi = ci; }
    else { s += cs*expf(cm-m); if (cm == m && ci < mi) mi = ci; }
  }
  sm[tid]=m; ss[tid]=s; si[tid]=mi;
  __syncthreads();
  for (int st=128; st>0; st>>=1){
    if (tid < st){
      float m2 = sm[tid+st], s2 = ss[tid+st]; int i2 = si[tid+st];
      if (m2 > sm[tid]){ ss[tid] = ss[tid]*expf(sm[tid]-m2) + s2; sm[tid]=m2; si[tid]=i2; }
      else if (m2 > -INFINITY){ ss[tid] += s2*expf(m2-sm[tid]); if (m2 == sm[tid] && i2 < si[tid]) si[tid]=i2; }
    }
    __syncthreads();
  }
  if (tid == 0){
    d_tok[b] = si[0];
    d_lseA[b*L + t] = sm[0] + logf(ss[0]);
  }
}

// ---------------- final: subtract lse from every logit row ----------------
// grid 2048 (one block per (b,t) row)
__global__ void k_sub(float* __restrict__ out){
  int row = blockIdx.x;
  float lse = d_lseA[row];
  float4* p = (float4*)(out + (size_t)row*V);
  for (int i = threadIdx.x; i < V/4; i += 256){
    float4 v = p[i];
    v.x -= lse; v.y -= lse; v.z -= lse; v.w -= lse;
    p[i] = v;
  }
}

// ---------------- launcher ----------------
extern "C" void kernel_launch(void* const* d_in, const int* in_sizes, int n_in,
                              void* d_out, int out_size){
  const int*   x         = (const int*)  d_in[0];
  const float* enc_embed = (const float*)d_in[1];
  const float* enc_wx    = (const float*)d_in[2];
  const float* enc_wh    = (const float*)d_in[3];
  const float* enc_b     = (const float*)d_in[4];
  const float* dec_embed = (const float*)d_in[5];
  const float* attn_w    = (const float*)d_in[6];
  const float* attn_b    = (const float*)d_in[7];
  const float* comb_w    = (const float*)d_in[8];
  const float* comb_b    = (const float*)d_in[9];
  const float* dec_wx    = (const float*)d_in[10];
  const float* dec_wh    = (const float*)d_in[11];
  const float* dec_b     = (const float*)d_in[12];
  const float* out_w     = (const float*)d_in[13];
  const float* out_b     = (const float*)d_in[14];
  float* out = (float*)d_out;

  u32 *p_owT, *p_whT, *p_gwT, *p_cwT, *p_xwT;
  cudaGetSymbolAddress((void**)&p_owT, d_owT);
  cudaGetSymbolAddress((void**)&p_whT, d_whT);
  cudaGetSymbolAddress((void**)&p_gwT, d_gwT);
  cudaGetSymbolAddress((void**)&p_cwT, d_cwT);
  cudaGetSymbolAddress((void**)&p_xwT, d_xwT);

  k_init<<<128,256>>>();
  k_T<<<500*16,256>>>(out_w,   V,  p_owT, 512,  0,   500);  // out_w^T
  k_T<<<64*16, 256>>>(enc_wh,  G4, p_whT, 512,  0,   64);   // enc_wh^T
  k_T<<<64*16, 256>>>(dec_wx,  G4, p_gwT, 1024, 0,   64);   // dec_wx^T (K 0..1023)
  k_T<<<64*16, 256>>>(dec_wh,  G4, p_gwT, 1024, 512, 64);   // dec_wh^T (K 1024..2047)
  k_T<<<16*32, 256>>>(comb_w,  H,  p_cwT, 1024, 0,   16);   // comb_w^T
  k_T<<<64*8,  256>>>(enc_wx,  G4, p_xwT, 256,  0,   64);   // enc_wx^T
  k_xg_mma<<<2048,256>>>(x, enc_embed, enc_b);
  for (int t=0;t<64;t++){
    k_mm_bf16<<<256,256>>>(0, nullptr);           // h @ enc_wh -> gpart
    k_enc_point<<<128,256>>>(t);
  }
  k_init<<<128,256>>>();
  for (int t=0;t<64;t++){
    k_attn1<<<256,256>>>(dec_embed, attn_w, t);   // prev-stats merge + logit partials
    k_attn_ctx<<<128,256>>>(attn_b);
    k_mm_bf16<<<64,256>>>(2, dec_embed);          // concat(e,ctx) @ comb_w -> cpart
    k_combfin<<<128,256>>>(comb_b);
    k_mm_bf16<<<256,256>>>(1, nullptr);           // concat(cin,h) @ [wx;wh] -> gpart
    k_dec_point<<<128,256>>>(dec_b);
    k_logits_mma<<<250,256>>>(out_b, out, t);
  }
  k_tok<<<32,256>>>(63);
  k_sub<<<2048,256>>>(out);
}

// round 16
// speedup vs baseline: 1.2825x; 1.0922x over previous
#include <cuda_runtime.h>
#include <math.h>
#include <stdint.h>

#define B 32
#define L 64
#define E 512
#define H 1024
#define G4 4096
#define V 32000

typedef unsigned int u32;
typedef unsigned short u16;
typedef unsigned long long u64;

// ---------------- scratch state (device globals; no allocs) ----------------
__device__ float d_h[B*H];               // decoder h (fp32, for attn)
__device__ float d_c[B*H];
__device__ u16   d_hbh[B*H];             // h as bf16 (GEMM A operand)
__device__ u16   d_cinbh[B*H];           // relu(combine) as bf16
__device__ float d_encouts[B*L*H];       // [b][l][j]
__device__ float d_xg[L][B][G4];         // precomputed emb@enc_wx + enc_b
__device__ float d_gpart[8][B][G4];      // K-split partials for gate GEMMs
__device__ float d_cpart[16][B][H];      // K-split partials for combine GEMM (16-way)
__device__ float d_ctx[B*H];             // attention context
__device__ float d_apart[8][B][64];      // attention logit partials
__device__ int   d_tok[B];
__device__ u32   d_owT[(size_t)V*512];   // out_w^T    [V][512]  bf16-pairs (64MB)
__device__ u32   d_whT[(size_t)G4*512];  // enc_wh^T   [4096][512]  (8MB)
__device__ u32   d_gwT[(size_t)G4*1024]; // [dec_wx;dec_wh]^T [4096][1024] (16MB)
__device__ u32   d_cwT[(size_t)H*1024];  // comb_w^T   [1024][1024] (4MB)
__device__ u32   d_xwT[(size_t)G4*256];  // enc_wx^T   [4096][256]  (4MB)
__device__ float d_lm2[B*250];           // per-(b,colchunk) max
__device__ float d_ls2[B*250];           // per-(b,colchunk) expsum
__device__ int   d_li2[B*250];           // per-(b,colchunk) argmax
__device__ float d_lseA[B*L];            // per-(b,t) log-sum-exp

__device__ __forceinline__ float sigmoidf_(float x){ return 1.f/(1.f+expf(-x)); }
__device__ __forceinline__ u32 f2bf(float f){ u32 b=__float_as_uint(f); return (b + 0x7fffu + ((b>>16)&1u))>>16; }

// classic tensor-core mma (sm_80+, suffix-free PTX -> compiles for sm_103)
__device__ __forceinline__ void mma_bf16(float* d, u32 a0,u32 a1,u32 a2,u32 a3,u32 b0,u32 b1){
  asm volatile("mma.sync.aligned.m16n8k16.row.col.f32.bf16.bf16.f32 "
    "{%0,%1,%2,%3}, {%4,%5,%6,%7}, {%8,%9}, {%0,%1,%2,%3};"
    : "+f"(d[0]),"+f"(d[1]),"+f"(d[2]),"+f"(d[3])
    : "r"(a0),"r"(a1),"r"(a2),"r"(a3),"r"(b0),"r"(b1));
}

// ---------------- init ----------------
__global__ void k_init(){
  int idx = blockIdx.x*256 + threadIdx.x;   // 32768 total
  d_h[idx]=0.f; d_c[idx]=0.f; d_hbh[idx]=0;
  if (idx < B) d_tok[idx] = 127;
}

// ---------------- one-time generic transpose-convert ----------------
// src fp32 [K][N] (row stride ns) -> dst u32 [N][kt] bf16-pairs at word offset k0w
__global__ void k_T(const float* __restrict__ src, int ns, u32* __restrict__ dst,
                    int kt, int k0w, int nblks){
  __shared__ float sh[64][65];
  int nb = blockIdx.x % nblks, kb = blockIdx.x / nblks;
  int n0 = nb*64, k0 = kb*64;
  int tid = threadIdx.x;
  int nc = tid & 63, kg = tid >> 6;
  #pragma unroll
  for (int r=0;r<16;r++){
    int kr = kg*16 + r;
    sh[kr][nc] = src[(size_t)(k0+kr)*ns + n0 + nc];
  }
  __syncthreads();
  int nl = tid >> 2, p0 = (tid & 3)*8;
  u32* d = dst + (size_t)(n0+nl)*kt + k0w + (k0>>1);
  #pragma unroll
  for (int q=0;q<8;q++){
    int p = p0 + q;
    d[p] = (f2bf(sh[2*p+1][nl])<<16) | f2bf(sh[2*p][nl]);
  }
}

// ---------------- one-time: xg[t] = emb(x_t) @ enc_wx + enc_b (bf16 mma) ----------------
// grid 2048 = 64 t x 32 colblk(128); 256 threads = 8 warps x 16 cols; K=512 in 4 chunks
__global__ void k_xg_mma(const int* __restrict__ x, const float* __restrict__ emb,
                         const float* __restrict__ eb){
  __shared__ u32 sA[32][68];
  __shared__ float sO[32][132];
  int tid = threadIdx.x, wid = tid>>5, lane = tid&31;
  int t = blockIdx.x >> 5;
  int colbase = (blockIdx.x & 31)*128;
  int g = lane>>2, q = lane&3;
  float acc[2][2][4] = {};
  const u32* wp = d_xwT + (size_t)(colbase + wid*16 + g)*256 + q;

  for (int kc=0;kc<4;kc++){
    int kb = kc*128;
    {
      int row = tid>>3, w0 = (tid&7)*8;
      int tok = x[row*L + t];
      const float2* ep = (const float2*)(emb + (size_t)tok*E + kb) + w0;
      #pragma unroll
      for (int i=0;i<8;i++){
        float2 v = ep[i];
        sA[row][w0+i] = (f2bf(v.y)<<16) | f2bf(v.x);
      }
    }
    __syncthreads();
    const u32* wkc = wp + kc*64;
    #pragma unroll
    for (int kss=0;kss<8;kss++){
      int kw = kss*8;
      u32 a00 = sA[g   ][kw+q],   a10 = sA[g+8 ][kw+q];
      u32 a20 = sA[g   ][kw+4+q], a30 = sA[g+8 ][kw+4+q];
      u32 a01 = sA[g+16][kw+q],   a11 = sA[g+24][kw+q];
      u32 a21 = sA[g+16][kw+4+q], a31 = sA[g+24][kw+4+q];
      #pragma unroll
      for (int j=0;j<2;j++){
        u32 b0 = wkc[j*8*256 + kw];
        u32 b1 = wkc[j*8*256 + kw + 4];
        mma_bf16(acc[0][j], a00,a10,a20,a30, b0,b1);
        mma_bf16(acc[1][j], a01,a11,a21,a31, b0,b1);
      }
    }
    __syncthreads();
  }
  #pragma unroll
  for (int m=0;m<2;m++)
    #pragma unroll
    for (int j=0;j<2;j++){
      int col = wid*16 + j*8 + q*2;
      *(float2*)&sO[g + m*16    ][col] = make_float2(acc[m][j][0], acc[m][j][1]);
      *(float2*)&sO[g + m*16 + 8][col] = make_float2(acc[m][j][2], acc[m][j][3]);
    }
  __syncthreads();
  int c0 = lane*4;
  float4 bb = *(const float4*)(eb + colbase + c0);
  #pragma unroll
  for (int rr=0;rr<4;rr++){
    int b = wid*4 + rr;
    float4 v = *(float4*)&sO[b][c0];
    v.x += bb.x; v.y += bb.y; v.z += bb.z; v.w += bb.w;
    *(float4*)&d_xg[t][b][colbase + c0] = v;
  }
}

// ---------------- generic bf16 mma GEMM: P[32 x 128cols] partials ----------------
// mode 0: enc gates  A=hbh          wT=d_whT kt=512  8ks x K128  out=d_gpart stride G4
// mode 1: dec gates  A=cinbh|hbh    wT=d_gwT kt=1024 8ks x K256  out=d_gpart stride G4
// mode 2: combine    A=e|ctx        wT=d_cwT kt=1024 16ks x K128 out=d_cpart stride H
// grid: mode0 256, mode1 256, mode2 128; 256 threads = 8 warps x 16 cols
__global__ void k_mm_bf16(int mode, const float* __restrict__ demb){
  __shared__ u32 sA[32][68];
  __shared__ float sO[32][132];
  int tid = threadIdx.x, wid = tid>>5, lane = tid&31;
  int ks, colbase;
  if (mode == 2){ ks = blockIdx.x & 15; colbase = (blockIdx.x >> 4)*128; }
  else          { ks = blockIdx.x & 7;  colbase = (blockIdx.x >> 3)*128; }
  int g = lane>>2, q = lane&3;
  const u32* wT; int kt, chunks; float* outp; int ostride;
  if (mode == 0){ wT = d_whT; kt = 512;  chunks = 1; outp = &d_gpart[0][0][0]; ostride = G4; }
  else if (mode == 1){ wT = d_gwT; kt = 1024; chunks = 2; outp = &d_gpart[0][0][0]; ostride = G4; }
  else { wT = d_cwT; kt = 1024; chunks = 1; outp = &d_cpart[0][0][0]; ostride = H; }

  float acc[2][2][4] = {};
  const u32* wp = wT + (size_t)(colbase + wid*16 + g)*kt + q;

  for (int kc=0; kc<chunks; kc++){
    int kb = (ks*chunks + kc)*128;
    {
      int row = tid>>3, w0 = (tid&7)*8;
      if (mode == 0){
        const uint4* hp = (const uint4*)(d_hbh + row*H + kb + w0*2);
        *(uint4*)&sA[row][w0]   = hp[0];
        *(uint4*)&sA[row][w0+4] = hp[1];
      } else if (mode == 1){
        const u16* src = (kb < H) ? (d_cinbh + row*H + kb) : (d_hbh + row*H + kb - H);
        const uint4* hp = (const uint4*)(src + w0*2);
        *(uint4*)&sA[row][w0]   = hp[0];
        *(uint4*)&sA[row][w0+4] = hp[1];
      } else {
        if (kb < H){
          int tok = d_tok[row];
          const float2* ep = (const float2*)(demb + (size_t)tok*H + kb);
          #pragma unroll
          for (int i=0;i<8;i++){
            float2 v = ep[w0+i];
            sA[row][w0+i] = (f2bf(v.y)<<16) | f2bf(v.x);
          }
        } else {
          const float2* cp = (const float2*)(d_ctx + row*H + (kb-H));
          #pragma unroll
          for (int i=0;i<8;i++){
            float2 v = cp[w0+i];
            sA[row][w0+i] = (f2bf(v.y)<<16) | f2bf(v.x);
          }
        }
      }
    }
    __syncthreads();
    const u32* wkc = wp + (ks*chunks + kc)*64;
    #pragma unroll
    for (int kss=0;kss<8;kss++){
      int kw = kss*8;
      u32 a00 = sA[g   ][kw+q],   a10 = sA[g+8 ][kw+q];
      u32 a20 = sA[g   ][kw+4+q], a30 = sA[g+8 ][kw+4+q];
      u32 a01 = sA[g+16][kw+q],   a11 = sA[g+24][kw+q];
      u32 a21 = sA[g+16][kw+4+q], a31 = sA[g+24][kw+4+q];
      #pragma unroll
      for (int j=0;j<2;j++){
        u32 b0 = wkc[(size_t)j*8*kt + kw];
        u32 b1 = wkc[(size_t)j*8*kt + kw + 4];
        mma_bf16(acc[0][j], a00,a10,a20,a30, b0,b1);
        mma_bf16(acc[1][j], a01,a11,a21,a31, b0,b1);
      }
    }
    __syncthreads();
  }
  #pragma unroll
  for (int m=0;m<2;m++)
    #pragma unroll
    for (int j=0;j<2;j++){
      int col = wid*16 + j*8 + q*2;
      *(float2*)&sO[g + m*16    ][col] = make_float2(acc[m][j][0], acc[m][j][1]);
      *(float2*)&sO[g + m*16 + 8][col] = make_float2(acc[m][j][2], acc[m][j][3]);
    }
  __syncthreads();
  #pragma unroll
  for (int rr=0;rr<4;rr++){
    int b = wid*4 + rr;
    int c0 = lane*4;
    float4 v = *(float4*)&sO[b][c0];
    *(float4*)(outp + (size_t)(ks*B + b)*ostride + colbase + c0) = v;
  }
}

// ---------------- encoder pointwise ----------------
__global__ void k_enc_point(int t){
  int idx = blockIdx.x*256 + threadIdx.x;
  int b = idx >> 10, j = idx & 1023;
  float g0 = d_xg[t][b][j],      g1 = d_xg[t][b][j+1024];
  float g2 = d_xg[t][b][j+2048], g3 = d_xg[t][b][j+3072];
  #pragma unroll
  for (int p=0;p<8;p++){
    g0 += d_gpart[p][b][j];      g1 += d_gpart[p][b][j+1024];
    g2 += d_gpart[p][b][j+2048]; g3 += d_gpart[p][b][j+3072];
  }
  float c = d_c[idx];
  c = sigmoidf_(g1)*c + sigmoidf_(g0)*tanhf(g2);
  float h = sigmoidf_(g3)*tanhf(c);
  d_c[idx]=c;
  d_hbh[idx] = (u16)f2bf(h);
  d_encouts[(b*L + t)*H + j] = h;
}

// ---------------- attention phase 1 (+ fused prev-step stats merge) ----------------
// grid 256 = 32 b x 8 ks (256 K each); 256 threads
__global__ void k_attn1(const float* __restrict__ demb, const float* __restrict__ aw_w,
                        int t){
  __shared__ float sm[256]; __shared__ float ss[256]; __shared__ int si[256];
  __shared__ float sp[256];
  int b = blockIdx.x >> 3, ks = blockIdx.x & 7;
  int tid = threadIdx.x;
  int tok;
  if (t > 0){
    // merge previous step's 250 logit-chunk stats (launch boundary = data ready)
    float m = -INFINITY, s = 0.f; int mi = 0x7fffffff;
    if (tid < 250){ m = d_lm2[b*250+tid]; s = d_ls2[b*250+tid]; mi = d_li2[b*250+tid]; }
    sm[tid]=m; ss[tid]=s; si[tid]=mi;
    __syncthreads();
    for (int st=128; st>0; st>>=1){
      if (tid < st){
        float m2 = sm[tid+st], s2 = ss[tid+st]; int i2 = si[tid+st];
        if (m2 > sm[tid]){ ss[tid] = ss[tid]*expf(sm[tid]-m2) + s2; sm[tid]=m2; si[tid]=i2; }
        else if (m2 > -INFINITY){ ss[tid] += s2*expf(m2-sm[tid]); if (m2 == sm[tid] && i2 < si[tid]) si[tid]=i2; }
      }
      __syncthreads();
    }
    tok = si[0];
    if (ks == 0 && tid == 0){
      d_tok[b] = tok;                              // for combine loader (next launch)
      d_lseA[b*L + (t-1)] = sm[0] + logf(ss[0]);
    }
    __syncthreads();
  } else {
    tok = 127;
  }
  const float* erow = demb + (size_t)tok*H;
  int col = tid & 63, kg = tid >> 6;
  int k0 = ks*256 + kg*64;
  float acc = 0.f;
  const float* arow = (k0 < H) ? (erow + k0) : (d_h + b*H + (k0-H));
  #pragma unroll 4
  for (int i=0;i<64;i++) acc += arow[i] * aw_w[(size_t)(k0+i)*64 + col];
  sp[tid] = acc;
  __syncthreads();
  if (tid < 64) d_apart[ks][b][tid] = sp[tid] + sp[tid+64] + sp[tid+128] + sp[tid+192];
}

// ---------------- attention phase 2: softmax + context ----------------
// grid 128 = 32 b x 4 jblk (256 j each)
__global__ void k_attn_ctx(const float* __restrict__ ab){
  __shared__ float s_aw[64];
  __shared__ float s_red[2];
  int b = blockIdx.x >> 2, jblk = blockIdx.x & 3;
  int tid = threadIdx.x;
  if (tid < 64){
    float lg = ab[tid];
    #pragma unroll
    for (int p=0;p<8;p++) lg += d_apart[p][b][tid];
    s_aw[tid] = lg;
  }
  __syncthreads();
  if (tid < 32){
    float m = fmaxf(s_aw[tid], s_aw[tid+32]);
    #pragma unroll
    for (int o=16;o>0;o>>=1) m = fmaxf(m, __shfl_xor_sync(0xffffffffu, m, o));
    if (tid==0) s_red[0]=m;
  }
  __syncthreads();
  if (tid < 64) s_aw[tid] = expf(s_aw[tid] - s_red[0]);
  __syncthreads();
  if (tid < 32){
    float s = s_aw[tid] + s_aw[tid+32];
    #pragma unroll
    for (int o=16;o>0;o>>=1) s += __shfl_xor_sync(0xffffffffu, s, o);
    if (tid==0) s_red[1]=s;
  }
  __syncthreads();
  float inv = 1.f / s_red[1];
  int j = jblk*256 + tid;
  float c = 0.f;
  #pragma unroll 4
  for (int l=0;l<64;l++) c += s_aw[l]*inv * d_encouts[(b*L + l)*H + j];
  d_ctx[b*H + j] = c;
}

// ---------------- combine finalize: reduce(16) + bias + relu -> bf16 ----------------
__global__ void k_combfin(const float* __restrict__ cb){
  int idx = blockIdx.x*256 + threadIdx.x;
  int b = idx >> 10, j = idx & 1023;
  float s = cb[j];
  #pragma unroll
  for (int p=0;p<16;p++) s += d_cpart[p][b][j];
  d_cinbh[idx] = (u16)f2bf(fmaxf(s, 0.f));
}

// ---------------- decoder pointwise ----------------
__global__ void k_dec_point(const float* __restrict__ db){
  int idx = blockIdx.x*256 + threadIdx.x;
  int b = idx >> 10, j = idx & 1023;
  float g0 = db[j], g1 = db[j+1024], g2 = db[j+2048], g3 = db[j+3072];
  #pragma unroll
  for (int p=0;p<8;p++){
    g0 += d_gpart[p][b][j];      g1 += d_gpart[p][b][j+1024];
    g2 += d_gpart[p][b][j+2048]; g3 += d_gpart[p][b][j+3072];
  }
  float c = d_c[idx];
  c = sigmoidf_(g1)*c + sigmoidf_(g0)*tanhf(g2);
  float h = sigmoidf_(g3)*tanhf(c);
  d_c[idx]=c; d_h[idx]=h;
  d_hbh[idx] = (u16)f2bf(h);
}

// ---------------- logits via mma.sync bf16 (double-buffered A) ----------------
// grid 250 (128 vocab cols each); 256 threads = 8 warps (warp w: cols w*16..w*16+15)
__global__ void k_logits_mma(const float* __restrict__ ob, float* __restrict__ out, int t){
  __shared__ u32 sA[2][32][68];
  __shared__ float sLg[32][132];
  int tid = threadIdx.x, wid = tid>>5, lane = tid&31;
  int colbase = blockIdx.x*128;
  int g = lane>>2, q = lane&3;
  int row = tid>>3, w0 = (tid&7)*8;
  float acc[2][2][4];
  #pragma unroll
  for (int m=0;m<2;m++)
    #pragma unroll
    for (int j=0;j<2;j++)
      #pragma unroll
      for (int r=0;r<4;r++) acc[m][j][r]=0.f;

  const u32* wp = d_owT + (size_t)(colbase + wid*16 + g)*512 + q;
  const uint4* hrow = (const uint4*)(d_hbh + row*H) + (w0>>2);   // +8 uint4 per chunk

  // prologue: chunk 0 -> buf 0
  {
    uint4 p0 = hrow[0], p1 = hrow[1];
    *(uint4*)&sA[0][row][w0]   = p0;
    *(uint4*)&sA[0][row][w0+4] = p1;
  }
  __syncthreads();

  for (int kc=0;kc<8;kc++){
    int cur = kc & 1;
    // prefetch next chunk (LDG issued before compute; latency hidden by MMAs)
    uint4 p0, p1;
    if (kc < 7){
      p0 = hrow[(kc+1)*8];
      p1 = hrow[(kc+1)*8 + 1];
    }
    const u32* wkc = wp + kc*64;
    #pragma unroll
    for (int ks=0;ks<8;ks++){
      int kw = ks*8;
      u32 a00 = sA[cur][g   ][kw+q],   a10 = sA[cur][g+8 ][kw+q];
      u32 a20 = sA[cur][g   ][kw+4+q], a30 = sA[cur][g+8 ][kw+4+q];
      u32 a01 = sA[cur][g+16][kw+q],   a11 = sA[cur][g+24][kw+q];
      u32 a21 = sA[cur][g+16][kw+4+q], a31 = sA[cur][g+24][kw+4+q];
      #pragma unroll
      for (int j=0;j<2;j++){
        u32 b0 = wkc[j*8*512 + kw];
        u32 b1 = wkc[j*8*512 + kw + 4];
        mma_bf16(acc[0][j], a00,a10,a20,a30, b0,b1);
        mma_bf16(acc[1][j], a01,a11,a21,a31, b0,b1);
      }
    }
    if (kc < 7){
      *(uint4*)&sA[cur^1][row][w0]   = p0;
      *(uint4*)&sA[cur^1][row][w0+4] = p1;
    }
    __syncthreads();
  }
  #pragma unroll
  for (int m=0;m<2;m++)
    #pragma unroll
    for (int j=0;j<2;j++){
      int col = wid*16 + j*8 + q*2;
      *(float2*)&sLg[g + m*16    ][col] = make_float2(acc[m][j][0], acc[m][j][1]);
      *(float2*)&sLg[g + m*16 + 8][col] = make_float2(acc[m][j][2], acc[m][j][3]);
    }
  __syncthreads();
  const float* bp = ob + colbase;
  float4 bb = *(const float4*)(bp + lane*4);
  #pragma unroll
  for (int rr=0;rr<4;rr++){
    int b = wid*4 + rr;
    int c0 = lane*4;
    float4 v = *(float4*)&sLg[b][c0];
    v.x += bb.x; v.y += bb.y; v.z += bb.z; v.w += bb.w;
    float* orow = out + ((size_t)(b*L + t))*V + colbase;
    *(float4*)(orow + c0) = v;
    float m = v.x; int mi = c0;
    if (v.y > m){ m=v.y; mi=c0+1; }
    if (v.z > m){ m=v.z; mi=c0+2; }
    if (v.w > m){ m=v.w; mi=c0+3; }
    #pragma unroll
    for (int o=16;o>0;o>>=1){
      float om = __shfl_xor_sync(0xffffffffu, m, o);
      int   oi = __shfl_xor_sync(0xffffffffu, mi, o);
      if (om > m || (om == m && oi < mi)){ m=om; mi=oi; }
    }
    float S = expf(v.x-m)+expf(v.y-m)+expf(v.z-m)+expf(v.w-m);
    #pragma unroll
    for (int o=16;o>0;o>>=1) S += __shfl_xor_sync(0xffffffffu, S, o);
    if (lane == 0){
      d_lm2[b*250 + blockIdx.x] = m;
      d_ls2[b*250 + blockIdx.x] = S;
      d_li2[b*250 + blockIdx.x] = colbase + mi;
    }
  }
}

// ---------------- final-step stats merge (t=63 lse) ----------------
// grid 32 (one block per batch row)
__global__ void k_tok(int t){
  __shared__ float sm[256]; __shared__ float ss[256]; __shared__ int si[256];
  int b = blockIdx.x, tid = threadIdx.x;
  float m = -INFINITY, s = 0.f; int mi = 0x7fffffff;
  for (int c = tid; c < 250; c += 256){
    float cm = d_lm2[b*250+c], cs = d_ls2[b*250+c]; int ci = d_li2[b*250+c];
    if (cm > m){ s = s*expf(m-cm) + cs; m = cm; mi = ci; }
    else { s += cs*expf(cm-m); if (cm == m && ci < mi) mi = ci; }
  }
  sm[tid]=m; ss[tid]=s; si[tid]=mi;
  __syncthreads();
  for (int st=128; st>0; st>>=1){
    if (tid < st){
      float m2 = sm[tid+st], s2 = ss[tid+st]; int i2 = si[tid+st];
      if (m2 > sm[tid]){ ss[tid] = ss[tid]*expf(sm[tid]-m2) + s2; sm[tid]=m2; si[tid]=i2; }
      else if (m2 > -INFINITY){ ss[tid] += s2*expf(m2-sm[tid]); if (m2 == sm[tid] && i2 < si[tid]) si[tid]=i2; }
    }
    __syncthreads();
  }
  if (tid == 0){
    d_tok[b] = si[0];
    d_lseA[b*L + t] = sm[0] + logf(ss[0]);
  }
}

// ---------------- final: subtract lse from every logit row ----------------
// grid 2048 (one block per (b,t) row)
__global__ void k_sub(float* __restrict__ out){
  int row = blockIdx.x;
  float lse = d_lseA[row];
  float4* p = (float4*)(out + (size_t)row*V);
  for (int i = threadIdx.x; i < V/4; i += 256){
    float4 v = p[i];
    v.x -= lse; v.y -= lse; v.z -= lse; v.w -= lse;
    p[i] = v;
  }
}

// ---------------- launcher ----------------
extern "C" void kernel_launch(void* const* d_in, const int* in_sizes, int n_in,
                              void* d_out, int out_size){
  const int*   x         = (const int*)  d_in[0];
  const float* enc_embed = (const float*)d_in[1];
  const float* enc_wx    = (const float*)d_in[2];
  const float* enc_wh    = (const float*)d_in[3];
  const float* enc_b     = (const float*)d_in[4];
  const float* dec_embed = (const float*)d_in[5];
  const float* attn_w    = (const float*)d_in[6];
  const float* attn_b    = (const float*)d_in[7];
  const float* comb_w    = (const float*)d_in[8];
  const float* comb_b    = (const float*)d_in[9];
  const float* dec_wx    = (const float*)d_in[10];
  const float* dec_wh    = (const float*)d_in[11];
  const float* dec_b     = (const float*)d_in[12];
  const float* out_w     = (const float*)d_in[13];
  const float* out_b     = (const float*)d_in[14];
  float* out = (float*)d_out;

  u32 *p_owT, *p_whT, *p_gwT, *p_cwT, *p_xwT;
  cudaGetSymbolAddress((void**)&p_owT, d_owT);
  cudaGetSymbolAddress((void**)&p_whT, d_whT);
  cudaGetSymbolAddress((void**)&p_gwT, d_gwT);
  cudaGetSymbolAddress((void**)&p_cwT, d_cwT);
  cudaGetSymbolAddress((void**)&p_xwT, d_xwT);

  k_init<<<128,256>>>();
  k_T<<<500*16,256>>>(out_w,   V,  p_owT, 512,  0,   500);  // out_w^T
  k_T<<<64*16, 256>>>(enc_wh,  G4, p_whT, 512,  0,   64);   // enc_wh^T
  k_T<<<64*16, 256>>>(dec_wx,  G4, p_gwT, 1024, 0,   64);   // dec_wx^T (K 0..1023)
  k_T<<<64*16, 256>>>(dec_wh,  G4, p_gwT, 1024, 512, 64);   // dec_wh^T (K 1024..2047)
  k_T<<<16*32, 256>>>(comb_w,  H,  p_cwT, 1024, 0,   16);   // comb_w^T
  k_T<<<64*8,  256>>>(enc_wx,  G4, p_xwT, 256,  0,   64);   // enc_wx^T
  k_xg_mma<<<2048,256>>>(x, enc_embed, enc_b);
  for (int t=0;t<64;t++){
    k_mm_bf16<<<256,256>>>(0, nullptr);           // h @ enc_wh -> gpart
    k_enc_point<<<128,256>>>(t);
  }
  k_init<<<128,256>>>();
  for (int t=0;t<64;t++){
    k_attn1<<<256,256>>>(dec_embed, attn_w, t);   // prev-stats merge + logit partials
    k_attn_ctx<<<128,256>>>(attn_b);
    k_mm_bf16<<<128,256>>>(2, dec_embed);         // concat(e,ctx) @ comb_w -> cpart (16-way)
    k_combfin<<<128,256>>>(comb_b);
    k_mm_bf16<<<256,256>>>(1, nullptr);           // concat(cin,h) @ [wx;wh] -> gpart
    k_dec_point<<<128,256>>>(dec_b);
    k_logits_mma<<<250,256>>>(out_b, out, t);
  }
  k_tok<<<32,256>>>(63);
  k_sub<<<2048,256>>>(out);
}